// round 7
// baseline (speedup 1.0000x reference)
#include <cuda_runtime.h>
#include <math.h>

#define NTOK 8192
#define H 2048
#define T 256
#define E 16
#define R 512

#define BM 128
#define BK 16
#define STG 3

// ---- scratch ----
__device__ float g_cnorm[E * T];
__device__ int   g_counts[E];
__device__ int   g_tok[E * NTOK];
__device__ float g_pstar[NTOK];
__device__ float g_dist[NTOK * T];
__device__ float g_h1[NTOK * R];
__device__ float g_h2[NTOK * H];
__device__ float g_ph[NTOK * H];   // premise tf32-hi (RNA-rounded)
__device__ float g_pl[NTOK * H];   // premise tf32-lo
__device__ float g_wh[H * T];      // Wdist tf32-hi
__device__ float g_wl[H * T];      // Wdist tf32-lo

__device__ __forceinline__ float gelu_f(float v) {
    return 0.5f * v * (1.0f + erff(v * 0.70710678118654752440f));
}
__device__ __forceinline__ unsigned f2tf(float x) {
    unsigned u; asm("cvt.rna.tf32.f32 %0, %1;" : "=r"(u) : "f"(x)); return u;
}
__device__ __forceinline__ void mma8(float* c, unsigned a0, unsigned a1, unsigned a2, unsigned a3,
                                     unsigned b0, unsigned b1) {
    asm volatile(
        "mma.sync.aligned.m16n8k8.row.col.f32.tf32.tf32.f32 "
        "{%0,%1,%2,%3}, {%4,%5,%6,%7}, {%8,%9}, {%0,%1,%2,%3};"
        : "+f"(c[0]), "+f"(c[1]), "+f"(c[2]), "+f"(c[3])
        : "r"(a0), "r"(a1), "r"(a2), "r"(a3), "r"(b0), "r"(b1));
}
__device__ __forceinline__ void cpa16(void* s, const void* g) {
    unsigned sa = (unsigned)__cvta_generic_to_shared(s);
    asm volatile("cp.async.cg.shared.global [%0], [%1], 16;" :: "r"(sa), "l"(g) : "memory");
}
#define CP_COMMIT() asm volatile("cp.async.commit_group;" ::: "memory")
#define CP_WAIT(n)  asm volatile("cp.async.wait_group %0;" :: "n"(n) : "memory")

// Wide-tile fragment compute: A pre-rounded (no cvt), B cvt.rna at load.
// Block tile 128x128, warp tile 32x64, acc[2][8][4].
__device__ __forceinline__ void compute_wide(
    float acc[2][8][4], const float (*A)[BK + 4], const float (*B)[128 + 8],
    int wm, int wn, int lane) {
    int r = lane >> 2, q = lane & 3;
#pragma unroll
    for (int s = 0; s < 2; s++) {
        unsigned a[2][4], b[8][2];
#pragma unroll
        for (int i = 0; i < 2; i++) {
            int row = wm * 32 + i * 16 + r;
            a[i][0] = __float_as_uint(A[row][s * 8 + q]);
            a[i][1] = __float_as_uint(A[row + 8][s * 8 + q]);
            a[i][2] = __float_as_uint(A[row][s * 8 + 4 + q]);
            a[i][3] = __float_as_uint(A[row + 8][s * 8 + 4 + q]);
        }
#pragma unroll
        for (int j = 0; j < 8; j++) {
            int col = wn * 64 + j * 8 + r;
            b[j][0] = f2tf(B[s * 8 + q][col]);
            b[j][1] = f2tf(B[s * 8 + 4 + q][col]);
        }
#pragma unroll
        for (int i = 0; i < 2; i++)
#pragma unroll
            for (int j = 0; j < 8; j++)
                mma8(acc[i][j], a[i][0], a[i][1], a[i][2], a[i][3], b[j][0], b[j][1]);
    }
}

// ---------------------------------------------------------------------------
// K0a: zero counters + normalize centroids
// ---------------------------------------------------------------------------
__global__ void prep_kernel(const float* __restrict__ centroids) {
    __shared__ float inv[E];
    int t = threadIdx.x;
    if (t < E) {
        g_counts[t] = 0;
        float ss = 0.f;
        const float* c = centroids + t * T;
        for (int j = 0; j < T; j++) { float v = c[j]; ss += v * v; }
        inv[t] = 1.0f / fmaxf(sqrtf(ss), 1e-8f);
    }
    __syncthreads();
    for (int idx = t; idx < E * T; idx += blockDim.x)
        g_cnorm[idx] = centroids[idx] * inv[idx / T];
}

// ---------------------------------------------------------------------------
// K0b: tf32 hi/lo split of premise and Wdist
// ---------------------------------------------------------------------------
__global__ __launch_bounds__(256) void split_kernel(
    const float* __restrict__ premise, const float* __restrict__ Wdist) {
    size_t i = (size_t)blockIdx.x * 256 + threadIdx.x;
    size_t np = (size_t)NTOK * H / 4;
    size_t nw = (size_t)H * T / 4;
    if (i < np) {
        float4 v = ((const float4*)premise)[i];
        float4 h, l;
        h.x = __uint_as_float(f2tf(v.x)); l.x = __uint_as_float(f2tf(v.x - h.x));
        h.y = __uint_as_float(f2tf(v.y)); l.y = __uint_as_float(f2tf(v.y - h.y));
        h.z = __uint_as_float(f2tf(v.z)); l.z = __uint_as_float(f2tf(v.z - h.z));
        h.w = __uint_as_float(f2tf(v.w)); l.w = __uint_as_float(f2tf(v.w - h.w));
        ((float4*)g_ph)[i] = h; ((float4*)g_pl)[i] = l;
    }
    if (i < nw) {
        float4 v = ((const float4*)Wdist)[i];
        float4 h, l;
        h.x = __uint_as_float(f2tf(v.x)); l.x = __uint_as_float(f2tf(v.x - h.x));
        h.y = __uint_as_float(f2tf(v.y)); l.y = __uint_as_float(f2tf(v.y - h.y));
        h.z = __uint_as_float(f2tf(v.z)); l.z = __uint_as_float(f2tf(v.z - h.z));
        h.w = __uint_as_float(f2tf(v.w)); l.w = __uint_as_float(f2tf(v.w - h.w));
        ((float4*)g_wh)[i] = h; ((float4*)g_wl)[i] = l;
    }
}

// ---------------------------------------------------------------------------
// K1: distill GEMM, 3xTF32 from pre-split hi/lo, cp.async pipeline.
// ---------------------------------------------------------------------------
__global__ __launch_bounds__(256) void distill_mma(const float* __restrict__ bdist) {
    __shared__ float Ah[STG][BM][BK + 4], Al[STG][BM][BK + 4];
    __shared__ float Bh[STG][BK][64 + 8], Bl[STG][BK][64 + 8];
    int tid = threadIdx.x, lane = tid & 31, warp = tid >> 5;
    int wm = warp >> 1, wn = warp & 1;
    int m0 = blockIdx.y * BM, n0 = blockIdx.x * 64;
    int arow = tid >> 2, akc = (tid & 3) * 4;
    int bkr = tid >> 4, bnc = (tid & 15) * 4;
    size_t rowA0 = (size_t)(m0 + arow) * H;
    size_t rowA1 = (size_t)(m0 + arow + 64) * H;

    float acc[2][4][4];
#pragma unroll
    for (int i = 0; i < 2; i++)
#pragma unroll
        for (int j = 0; j < 4; j++)
#pragma unroll
            for (int z = 0; z < 4; z++) acc[i][j][z] = 0.f;

    const int NT = H / BK;
#pragma unroll
    for (int s = 0; s < STG - 1; s++) {
        int k0 = s * BK;
        cpa16(&Ah[s][arow][akc], &g_ph[rowA0 + k0 + akc]);
        cpa16(&Ah[s][arow + 64][akc], &g_ph[rowA1 + k0 + akc]);
        cpa16(&Al[s][arow][akc], &g_pl[rowA0 + k0 + akc]);
        cpa16(&Al[s][arow + 64][akc], &g_pl[rowA1 + k0 + akc]);
        cpa16(&Bh[s][bkr][bnc], &g_wh[(size_t)(k0 + bkr) * T + n0 + bnc]);
        cpa16(&Bl[s][bkr][bnc], &g_wl[(size_t)(k0 + bkr) * T + n0 + bnc]);
        CP_COMMIT();
    }
    for (int it = 0; it < NT; it++) {
        CP_WAIT(STG - 2);
        __syncthreads();
        int ld = it + STG - 1;
        if (ld < NT) {
            int st = ld % STG; int k0 = ld * BK;
            cpa16(&Ah[st][arow][akc], &g_ph[rowA0 + k0 + akc]);
            cpa16(&Ah[st][arow + 64][akc], &g_ph[rowA1 + k0 + akc]);
            cpa16(&Al[st][arow][akc], &g_pl[rowA0 + k0 + akc]);
            cpa16(&Al[st][arow + 64][akc], &g_pl[rowA1 + k0 + akc]);
            cpa16(&Bh[st][bkr][bnc], &g_wh[(size_t)(k0 + bkr) * T + n0 + bnc]);
            cpa16(&Bl[st][bkr][bnc], &g_wl[(size_t)(k0 + bkr) * T + n0 + bnc]);
        }
        CP_COMMIT();
        int buf = it % STG;
        int r = lane >> 2, q = lane & 3;
#pragma unroll
        for (int s = 0; s < 2; s++) {
            unsigned ah[2][4], al[2][4], bh[4][2], bl[4][2];
#pragma unroll
            for (int i = 0; i < 2; i++) {
                int row = wm * 32 + i * 16 + r;
                ah[i][0] = __float_as_uint(Ah[buf][row][s * 8 + q]);
                ah[i][1] = __float_as_uint(Ah[buf][row + 8][s * 8 + q]);
                ah[i][2] = __float_as_uint(Ah[buf][row][s * 8 + 4 + q]);
                ah[i][3] = __float_as_uint(Ah[buf][row + 8][s * 8 + 4 + q]);
                al[i][0] = __float_as_uint(Al[buf][row][s * 8 + q]);
                al[i][1] = __float_as_uint(Al[buf][row + 8][s * 8 + q]);
                al[i][2] = __float_as_uint(Al[buf][row][s * 8 + 4 + q]);
                al[i][3] = __float_as_uint(Al[buf][row + 8][s * 8 + 4 + q]);
            }
#pragma unroll
            for (int j = 0; j < 4; j++) {
                int col = wn * 32 + j * 8 + r;
                bh[j][0] = __float_as_uint(Bh[buf][s * 8 + q][col]);
                bh[j][1] = __float_as_uint(Bh[buf][s * 8 + 4 + q][col]);
                bl[j][0] = __float_as_uint(Bl[buf][s * 8 + q][col]);
                bl[j][1] = __float_as_uint(Bl[buf][s * 8 + 4 + q][col]);
            }
#pragma unroll
            for (int i = 0; i < 2; i++)
#pragma unroll
                for (int j = 0; j < 4; j++) {
                    mma8(acc[i][j], ah[i][0], ah[i][1], ah[i][2], ah[i][3], bh[j][0], bh[j][1]);
                    mma8(acc[i][j], ah[i][0], ah[i][1], ah[i][2], ah[i][3], bl[j][0], bl[j][1]);
                    mma8(acc[i][j], al[i][0], al[i][1], al[i][2], al[i][3], bh[j][0], bh[j][1]);
                }
        }
    }
#pragma unroll
    for (int i = 0; i < 2; i++) {
        int row = m0 + wm * 32 + i * 16 + (lane >> 2);
#pragma unroll
        for (int j = 0; j < 4; j++) {
            int col = n0 + wn * 32 + j * 8 + (lane & 3) * 2;
            float b0 = bdist[col], b1 = bdist[col + 1];
            float2 o0, o1;
            o0.x = gelu_f(acc[i][j][0] + b0); o0.y = gelu_f(acc[i][j][1] + b1);
            o1.x = gelu_f(acc[i][j][2] + b0); o1.y = gelu_f(acc[i][j][3] + b1);
            *(float2*)&g_dist[(size_t)row * T + col] = o0;
            *(float2*)&g_dist[(size_t)(row + 8) * T + col] = o1;
        }
    }
}

// ---------------------------------------------------------------------------
// K2: routing decisions. One warp per token.
// ---------------------------------------------------------------------------
__global__ __launch_bounds__(256) void route_kernel() {
    __shared__ float cn[E][T];
    int tid = threadIdx.x;
    for (int idx = tid; idx < E * T; idx += 256) cn[idx >> 8][idx & 255] = g_cnorm[idx];
    __syncthreads();
    int warp = tid >> 5, lane = tid & 31;
    int tok = blockIdx.x * 8 + warp;

    float d[8];
#pragma unroll
    for (int i = 0; i < 8; i++) d[i] = g_dist[(size_t)tok * T + lane + 32 * i];
    float ss = 0.f;
#pragma unroll
    for (int i = 0; i < 8; i++) ss += d[i] * d[i];
#pragma unroll
    for (int o = 16; o; o >>= 1) ss += __shfl_xor_sync(0xffffffffu, ss, o);
    float inv = 1.0f / fmaxf(sqrtf(ss), 1e-8f);

    float mydot = 0.f;
#pragma unroll
    for (int ee = 0; ee < E; ee++) {
        float p = 0.f;
#pragma unroll
        for (int i = 0; i < 8; i++) p = fmaf(d[i], cn[ee][lane + 32 * i], p);
#pragma unroll
        for (int o = 16; o; o >>= 1) p += __shfl_xor_sync(0xffffffffu, p, o);
        if (lane == ee) mydot = p;
    }
    float logit = -1e30f;
    if (lane < E) {
        float dot = mydot * inv;
        float dist = sqrtf(fmaxf(2.f - 2.f * dot, 0.f));
        logit = -dist;
    }
    float mx = logit;
#pragma unroll
    for (int o = 16; o; o >>= 1) mx = fmaxf(mx, __shfl_xor_sync(0xffffffffu, mx, o));
    float ex = (lane < E) ? expf(logit - mx) : 0.f;
    float sum = ex;
#pragma unroll
    for (int o = 16; o; o >>= 1) sum += __shfl_xor_sync(0xffffffffu, sum, o);
    float prob = ex / sum;

    float p1 = prob; int i1 = lane;
#pragma unroll
    for (int o = 16; o; o >>= 1) {
        float po = __shfl_xor_sync(0xffffffffu, p1, o);
        int   io = __shfl_xor_sync(0xffffffffu, i1, o);
        if (po > p1 || (po == p1 && io < i1)) { p1 = po; i1 = io; }
    }
    float p2 = (lane == i1) ? -1.f : prob; int i2 = lane;
#pragma unroll
    for (int o = 16; o; o >>= 1) {
        float po = __shfl_xor_sync(0xffffffffu, p2, o);
        int   io = __shfl_xor_sync(0xffffffffu, i2, o);
        if (po > p2 || (po == p2 && io < i2)) { p2 = po; i2 = io; }
    }
    int e_star = max(i1, i2);
    float p_star = (e_star == i1) ? p1 : p2;
    if (lane == 0) {
        g_pstar[tok] = p_star;
        int pos = atomicAdd(&g_counts[e_star], 1);
        g_tok[e_star * NTOK + pos] = tok;
    }
}

// ---------------------------------------------------------------------------
// K3: gathered GEMM h1 = gelu(X_e @ Wd[e]). 128x128, A=g_ph (pre-rounded).
// Epilogue writes g_h1 RNA-rounded so the h2 GEMM needs no A-cvt.
// ---------------------------------------------------------------------------
__global__ __launch_bounds__(256) void expert_gemm1(const float* __restrict__ Wd) {
    int e = blockIdx.z;
    int cnt = g_counts[e];
    __shared__ float As[STG][BM][BK + 4];
    __shared__ float Bs[STG][BK][128 + 8];
    __shared__ int toks[BM];
    int tid = threadIdx.x, lane = tid & 31, warp = tid >> 5;
    int wm = warp >> 1, wn = warp & 1;
    const float* Wde = Wd + (size_t)e * H * R;
    int n0 = blockIdx.x * 128;
    int arow = tid >> 2, akc = (tid & 3) * 4;
    int bkr = tid >> 4, bnc = (tid & 15) * 8;

    for (int m0 = blockIdx.y * BM; m0 < cnt; m0 += gridDim.y * BM) {
        __syncthreads();
        if (tid < BM) toks[tid] = g_tok[e * NTOK + min(m0 + tid, cnt - 1)];
        __syncthreads();
        size_t rowA0 = (size_t)toks[arow] * H;
        size_t rowA1 = (size_t)toks[arow + 64] * H;
        float acc[2][8][4];
#pragma unroll
        for (int i = 0; i < 2; i++)
#pragma unroll
            for (int j = 0; j < 8; j++)
#pragma unroll
                for (int z = 0; z < 4; z++) acc[i][j][z] = 0.f;

        const int NT = H / BK;
#pragma unroll
        for (int s = 0; s < STG - 1; s++) {
            int k0 = s * BK;
            cpa16(&As[s][arow][akc], &g_ph[rowA0 + k0 + akc]);
            cpa16(&As[s][arow + 64][akc], &g_ph[rowA1 + k0 + akc]);
            cpa16(&Bs[s][bkr][bnc], &Wde[(size_t)(k0 + bkr) * R + n0 + bnc]);
            cpa16(&Bs[s][bkr][bnc + 4], &Wde[(size_t)(k0 + bkr) * R + n0 + bnc + 4]);
            CP_COMMIT();
        }
        for (int it = 0; it < NT; it++) {
            CP_WAIT(STG - 2);
            __syncthreads();
            int ld = it + STG - 1;
            if (ld < NT) {
                int st = ld % STG; int k0 = ld * BK;
                cpa16(&As[st][arow][akc], &g_ph[rowA0 + k0 + akc]);
                cpa16(&As[st][arow + 64][akc], &g_ph[rowA1 + k0 + akc]);
                cpa16(&Bs[st][bkr][bnc], &Wde[(size_t)(k0 + bkr) * R + n0 + bnc]);
                cpa16(&Bs[st][bkr][bnc + 4], &Wde[(size_t)(k0 + bkr) * R + n0 + bnc + 4]);
            }
            CP_COMMIT();
            compute_wide(acc, As[it % STG], Bs[it % STG], wm, wn, lane);
        }
#pragma unroll
        for (int i = 0; i < 2; i++) {
            int rl0 = wm * 32 + i * 16 + (lane >> 2);
#pragma unroll
            for (int j = 0; j < 8; j++) {
                int col = n0 + wn * 64 + j * 8 + (lane & 3) * 2;
                if (m0 + rl0 < cnt) {
                    float2 o;
                    o.x = __uint_as_float(f2tf(gelu_f(acc[i][j][0])));
                    o.y = __uint_as_float(f2tf(gelu_f(acc[i][j][1])));
                    *(float2*)&g_h1[(size_t)toks[rl0] * R + col] = o;
                }
                if (m0 + rl0 + 8 < cnt) {
                    float2 o;
                    o.x = __uint_as_float(f2tf(gelu_f(acc[i][j][2])));
                    o.y = __uint_as_float(f2tf(gelu_f(acc[i][j][3])));
                    *(float2*)&g_h1[(size_t)toks[rl0 + 8] * R + col] = o;
                }
            }
        }
    }
}

// ---------------------------------------------------------------------------
// K4: h2 = h1 @ Wu[e]  (K = R). 128x128 wide tile. A = g_h1 (pre-rounded).
// ---------------------------------------------------------------------------
__global__ __launch_bounds__(256) void expert_h2(const float* __restrict__ Wu) {
    int e = blockIdx.z;
    int cnt = g_counts[e];
    __shared__ float As[STG][BM][BK + 4];
    __shared__ float Bs[STG][BK][128 + 8];
    __shared__ int toks[BM];
    int tid = threadIdx.x, lane = tid & 31, warp = tid >> 5;
    int wm = warp >> 1, wn = warp & 1;
    const float* Wue = Wu + (size_t)e * R * H;
    int n0 = blockIdx.x * 128;
    int arow = tid >> 2, akc = (tid & 3) * 4;
    int bkr = tid >> 4, bnc = (tid & 15) * 8;

    for (int m0 = blockIdx.y * BM; m0 < cnt; m0 += gridDim.y * BM) {
        __syncthreads();
        if (tid < BM) toks[tid] = g_tok[e * NTOK + min(m0 + tid, cnt - 1)];
        __syncthreads();
        size_t rowA0 = (size_t)toks[arow] * R;
        size_t rowA1 = (size_t)toks[arow + 64] * R;
        float acc[2][8][4];
#pragma unroll
        for (int i = 0; i < 2; i++)
#pragma unroll
            for (int j = 0; j < 8; j++)
#pragma unroll
                for (int z = 0; z < 4; z++) acc[i][j][z] = 0.f;

        const int NT = R / BK;
#pragma unroll
        for (int s = 0; s < STG - 1; s++) {
            int k0 = s * BK;
            cpa16(&As[s][arow][akc], &g_h1[rowA0 + k0 + akc]);
            cpa16(&As[s][arow + 64][akc], &g_h1[rowA1 + k0 + akc]);
            cpa16(&Bs[s][bkr][bnc], &Wue[(size_t)(k0 + bkr) * H + n0 + bnc]);
            cpa16(&Bs[s][bkr][bnc + 4], &Wue[(size_t)(k0 + bkr) * H + n0 + bnc + 4]);
            CP_COMMIT();
        }
        for (int it = 0; it < NT; it++) {
            CP_WAIT(STG - 2);
            __syncthreads();
            int ld = it + STG - 1;
            if (ld < NT) {
                int st = ld % STG; int k0 = ld * BK;
                cpa16(&As[st][arow][akc], &g_h1[rowA0 + k0 + akc]);
                cpa16(&As[st][arow + 64][akc], &g_h1[rowA1 + k0 + akc]);
                cpa16(&Bs[st][bkr][bnc], &Wue[(size_t)(k0 + bkr) * H + n0 + bnc]);
                cpa16(&Bs[st][bkr][bnc + 4], &Wue[(size_t)(k0 + bkr) * H + n0 + bnc + 4]);
            }
            CP_COMMIT();
            compute_wide(acc, As[it % STG], Bs[it % STG], wm, wn, lane);
        }
#pragma unroll
        for (int i = 0; i < 2; i++) {
            int rl0 = wm * 32 + i * 16 + (lane >> 2);
#pragma unroll
            for (int j = 0; j < 8; j++) {
                int col = n0 + wn * 64 + j * 8 + (lane & 3) * 2;
                if (m0 + rl0 < cnt) {
                    float2 o; o.x = acc[i][j][0]; o.y = acc[i][j][1];
                    *(float2*)&g_h2[(size_t)toks[rl0] * H + col] = o;
                }
                if (m0 + rl0 + 8 < cnt) {
                    float2 o; o.x = acc[i][j][2]; o.y = acc[i][j][3];
                    *(float2*)&g_h2[(size_t)toks[rl0 + 8] * H + col] = o;
                }
            }
        }
    }
}

// ---------------------------------------------------------------------------
// K5: gate GEMM + highway epilogue. glog = x @ Wg[e] (K = H), A = g_ph.
// out = p* * (sigmoid(glog+bg)*h2 + (1-sigmoid)*x)
// ---------------------------------------------------------------------------
__global__ __launch_bounds__(256) void expert_g(
    const float* __restrict__ premise,
    const float* __restrict__ Wg,
    const float* __restrict__ bg,
    float* __restrict__ out) {
    int e = blockIdx.z;
    int cnt = g_counts[e];
    __shared__ float As[STG][BM][BK + 4];
    __shared__ float Bs[STG][BK][128 + 8];
    __shared__ int toks[BM];
    int tid = threadIdx.x, lane = tid & 31, warp = tid >> 5;
    int wm = warp >> 1, wn = warp & 1;
    const float* Wge = Wg + (size_t)e * H * H;
    int n0 = blockIdx.x * 128;
    int arow = tid >> 2, akc = (tid & 3) * 4;
    int bkr = tid >> 4, bnc = (tid & 15) * 8;

    for (int m0 = blockIdx.y * BM; m0 < cnt; m0 += gridDim.y * BM) {
        __syncthreads();
        if (tid < BM) toks[tid] = g_tok[e * NTOK + min(m0 + tid, cnt - 1)];
        __syncthreads();
        size_t rowA0 = (size_t)toks[arow] * H;
        size_t rowA1 = (size_t)toks[arow + 64] * H;
        float acc[2][8][4];
#pragma unroll
        for (int i = 0; i < 2; i++)
#pragma unroll
            for (int j = 0; j < 8; j++)
#pragma unroll
                for (int z = 0; z < 4; z++) acc[i][j][z] = 0.f;

        const int NT = H / BK;
#pragma unroll
        for (int s = 0; s < STG - 1; s++) {
            int k0 = s * BK;
            cpa16(&As[s][arow][akc], &g_ph[rowA0 + k0 + akc]);
            cpa16(&As[s][arow + 64][akc], &g_ph[rowA1 + k0 + akc]);
            cpa16(&Bs[s][bkr][bnc], &Wge[(size_t)(k0 + bkr) * H + n0 + bnc]);
            cpa16(&Bs[s][bkr][bnc + 4], &Wge[(size_t)(k0 + bkr) * H + n0 + bnc + 4]);
            CP_COMMIT();
        }
        for (int it = 0; it < NT; it++) {
            CP_WAIT(STG - 2);
            __syncthreads();
            int ld = it + STG - 1;
            if (ld < NT) {
                int st = ld % STG; int k0 = ld * BK;
                cpa16(&As[st][arow][akc], &g_ph[rowA0 + k0 + akc]);
                cpa16(&As[st][arow + 64][akc], &g_ph[rowA1 + k0 + akc]);
                cpa16(&Bs[st][bkr][bnc], &Wge[(size_t)(k0 + bkr) * H + n0 + bnc]);
                cpa16(&Bs[st][bkr][bnc + 4], &Wge[(size_t)(k0 + bkr) * H + n0 + bnc + 4]);
            }
            CP_COMMIT();
            compute_wide(acc, As[it % STG], Bs[it % STG], wm, wn, lane);
        }
        // epilogue
#pragma unroll
        for (int i = 0; i < 2; i++) {
            int rl0 = wm * 32 + i * 16 + (lane >> 2);
#pragma unroll
            for (int half = 0; half < 2; half++) {
                int rl = rl0 + half * 8;
                if (m0 + rl < cnt) {
                    int tok = toks[rl];
                    float p = g_pstar[tok];
#pragma unroll
                    for (int j = 0; j < 8; j++) {
                        int col = n0 + wn * 64 + j * 8 + (lane & 3) * 2;
                        float2 bgv = *(const float2*)&bg[(size_t)e * H + col];
                        float2 xv = *(const float2*)&premise[(size_t)tok * H + col];
                        float2 hv = *(const float2*)&g_h2[(size_t)tok * H + col];
                        float z0 = acc[i][j][half * 2] + bgv.x;
                        float z1 = acc[i][j][half * 2 + 1] + bgv.y;
                        float gg0 = 1.0f / (1.0f + expf(-z0));
                        float gg1 = 1.0f / (1.0f + expf(-z1));
                        float2 o;
                        o.x = p * (gg0 * hv.x + (1.0f - gg0) * xv.x);
                        o.y = p * (gg1 * hv.y + (1.0f - gg1) * xv.y);
                        *(float2*)&out[(size_t)tok * H + col] = o;
                    }
                }
            }
        }
    }
}

// ---------------------------------------------------------------------------
extern "C" void kernel_launch(void* const* d_in, const int* in_sizes, int n_in,
                              void* d_out, int out_size) {
    const float* premise   = (const float*)d_in[0];
    const float* Wdist     = (const float*)d_in[1];
    const float* bdist     = (const float*)d_in[2];
    const float* centroids = (const float*)d_in[3];
    const float* Wd        = (const float*)d_in[4];
    const float* Wu        = (const float*)d_in[5];
    const float* Wg        = (const float*)d_in[6];
    const float* bg        = (const float*)d_in[7];
    float* out = (float*)d_out;

    prep_kernel<<<1, 256>>>(centroids);
    split_kernel<<<(NTOK * H / 4 + 255) / 256, 256>>>(premise, Wdist);
    distill_mma<<<dim3(T / 64, NTOK / BM), 256>>>(bdist);
    route_kernel<<<NTOK / 8, 256>>>();
    expert_gemm1<<<dim3(R / 128, 4, E), 256>>>(Wd);
    expert_h2<<<dim3(H / 128, 4, E), 256>>>(Wu);
    expert_g<<<dim3(H / 128, 4, E), 256>>>(premise, Wg, bg, out);
}